// round 15
// baseline (speedup 1.0000x reference)
#include <cuda_runtime.h>
#include <cstdint>

#define NL 32
#define DM 1024
#define NK 4
#define IQO 1024
#define IKV 256
#define IFF 2816

#define XCHUNK_B 12288                // 768 quads, e-major: ((e*3+p)*64 + cc)*16
#define WRING_OFF (2 * XCHUNK_B)      // 24576
#define WRING_WARP 10240              // 5 slots x 2048 B
#define SMEM_BYTES (WRING_OFF + 8 * WRING_WARP)   // 106496
#define NCOPY 128

// -------- transposed MLP x scratch + replay-safe handshake --------
// quad (l*11 + c)*768 + (e*3+p)*64 + ccl = x[j=4p..4p+3] at elem ((c*64+ccl)*4+e)
__device__ float4 g_xt_mlp[NL * 11 * 768];
__device__ int g_ready[NL];       // transposes done per layer (0..11)
__device__ int g_consumed[NL];    // MLP consumers done per layer (0..16)

// -------- helpers --------
__device__ __forceinline__ void ffma2(unsigned long long &d,
                                      unsigned long long a,
                                      unsigned long long b) {
    asm("fma.rn.f32x2 %0, %1, %2, %0;" : "+l"(d) : "l"(a), "l"(b));
}
__device__ __forceinline__ unsigned long long fdup(float f) {
    unsigned long long r;
    asm("mov.b64 %0, {%1, %1};" : "=l"(r) : "f"(f));
    return r;
}
__device__ __forceinline__ void unpack2(unsigned long long v, float &lo, float &hi) {
    asm("mov.b64 {%0, %1}, %2;" : "=f"(lo), "=f"(hi) : "l"(v));
}
__device__ __forceinline__ float getf(float4 v, int e) {
    return (e == 0) ? v.x : (e == 1) ? v.y : (e == 2) ? v.z : v.w;
}
__device__ __forceinline__ float hsum16(float v) {
    v += __shfl_xor_sync(0xffffffffu, v, 8);
    v += __shfl_xor_sync(0xffffffffu, v, 4);
    v += __shfl_xor_sync(0xffffffffu, v, 2);
    v += __shfl_xor_sync(0xffffffffu, v, 1);
    return v;
}
__device__ __forceinline__ void cpasync16(uint32_t dst, const void* src) {
    asm volatile("cp.async.cg.shared.global [%0], [%1], 16;" :: "r"(dst), "l"(src));
}
#define CP_COMMIT() asm volatile("cp.async.commit_group;" ::: "memory")
__device__ __forceinline__ void cp_wait3() {
    asm volatile("cp.async.wait_group 3;" ::: "memory");
}

// ---- Transpose block: one (l, c) MLP tile, coalesced both sides ----
__device__ void transpose_block(const float* __restrict__ cm,
                                int b, char* sm, int tid)
{
    float4* tile = reinterpret_cast<float4*>(sm);
    float* tf = reinterpret_cast<float*>(sm);
    const int l = b / 11, c = b - l * 11;
    const float4* cm4 = reinterpret_cast<const float4*>(cm) +
                        (size_t)l * 12 * 704 + c * 64;
    #pragma unroll
    for (int k = 0; k < 3; k++) {
        const int idx = tid + k * 256;
        const int j = idx >> 6, ccl = idx & 63;
        float4 v = __ldcs(cm4 + (size_t)j * 704 + ccl);
        const int p = j >> 2, kk = j & 3;
        tf[((0 * 3 + p) * 64 + ccl) * 4 + kk] = v.x;
        tf[((1 * 3 + p) * 64 + ccl) * 4 + kk] = v.y;
        tf[((2 * 3 + p) * 64 + ccl) * 4 + kk] = v.z;
        tf[((3 * 3 + p) * 64 + ccl) * 4 + kk] = v.w;
    }
    __syncthreads();
    float4* dst = g_xt_mlp + (size_t)b * 768;
    #pragma unroll
    for (int k = 0; k < 3; k++) dst[tid + k * 256] = tile[tid + k * 256];
    __threadfence();
    __syncthreads();
    if (tid == 0) atomicAdd(&g_ready[l], 1);
}

// ---- MLP module: 8 warps x 8 rows = 64 rows/CTA; 12 RHS packed FFMA2 ----
__device__ void mlp_block(const float* __restrict__ Wd,
                          float* __restrict__ out,
                          int l, int dt,
                          char* sm, uint32_t smem_u,
                          int tid, int lane, int wid)
{
    // Wait for this layer's 11 transpose tiles (replay-safe counters).
    if (tid == 0) {
        while (atomicAdd(&g_ready[l], 0) < 11) { }
    }
    __syncthreads();
    __threadfence();   // acquire

    const int rh = lane >> 4;
    const int col = lane & 15;
    const float* wbase = Wd + ((size_t)l * DM + dt * 64 + wid * 8) * IFF;
    const uint32_t wring_u = smem_u + WRING_OFF + wid * WRING_WARP;
    const char* wring = sm + WRING_OFF + wid * WRING_WARP;
    const float4* xg4 = g_xt_mlp + (size_t)l * 11 * 768;

    auto wstep = [&](int s) {
        if (s < 44) {
            const uint32_t dst = wring_u + (s % 5) * 2048 + (rh * 64 + col) * 16;
            const float* src = wbase + (size_t)(rh * 4) * IFF + (s * 16 + col) * 4;
            #pragma unroll
            for (int q = 0; q < 4; q++)
                cpasync16(dst + q * 256, src + (size_t)q * IFF);
        }
        CP_COMMIT();
    };

    float4 pre[3];
    #pragma unroll
    for (int k = 0; k < 3; k++) pre[k] = xg4[tid + k * 256];

    wstep(0); wstep(1); wstep(2); wstep(3);

    unsigned long long acc[4][6];
    #pragma unroll
    for (int q = 0; q < 4; q++)
        #pragma unroll
        for (int p = 0; p < 6; p++) acc[q][p] = 0ull;

    for (int c = 0; c < 11; ++c) {
        float4* xb = reinterpret_cast<float4*>(sm + (c & 1) * XCHUNK_B);
        #pragma unroll
        for (int k = 0; k < 3; k++) xb[tid + k * 256] = pre[k];
        __syncthreads();
        if (c < 10) {
            #pragma unroll
            for (int k = 0; k < 3; k++) pre[k] = xg4[(c + 1) * 768 + tid + k * 256];
        }
        #pragma unroll
        for (int it = 0; it < 4; ++it) {
            const int s = c * 4 + it;
            cp_wait3();
            const char* wq = wring + (s % 5) * 2048;
            float4 w0 = *reinterpret_cast<const float4*>(wq + (rh * 64 + 0 * 16 + col) * 16);
            float4 w1 = *reinterpret_cast<const float4*>(wq + (rh * 64 + 1 * 16 + col) * 16);
            float4 w2 = *reinterpret_cast<const float4*>(wq + (rh * 64 + 2 * 16 + col) * 16);
            float4 w3 = *reinterpret_cast<const float4*>(wq + (rh * 64 + 3 * 16 + col) * 16);
            wstep(s + 4);
            const char* xp = reinterpret_cast<const char*>(xb) + (it * 16 + col) * 16;
            #pragma unroll
            for (int e = 0; e < 4; e++) {
                ulonglong2 x0 = *reinterpret_cast<const ulonglong2*>(xp + (e * 3 + 0) * 1024);
                ulonglong2 x1 = *reinterpret_cast<const ulonglong2*>(xp + (e * 3 + 1) * 1024);
                ulonglong2 x2 = *reinterpret_cast<const ulonglong2*>(xp + (e * 3 + 2) * 1024);
                unsigned long long d0 = fdup(getf(w0, e));
                unsigned long long d1 = fdup(getf(w1, e));
                unsigned long long d2 = fdup(getf(w2, e));
                unsigned long long d3 = fdup(getf(w3, e));
                ffma2(acc[0][0], d0, x0.x); ffma2(acc[0][1], d0, x0.y);
                ffma2(acc[0][2], d0, x1.x); ffma2(acc[0][3], d0, x1.y);
                ffma2(acc[0][4], d0, x2.x); ffma2(acc[0][5], d0, x2.y);
                ffma2(acc[1][0], d1, x0.x); ffma2(acc[1][1], d1, x0.y);
                ffma2(acc[1][2], d1, x1.x); ffma2(acc[1][3], d1, x1.y);
                ffma2(acc[1][4], d1, x2.x); ffma2(acc[1][5], d1, x2.y);
                ffma2(acc[2][0], d2, x0.x); ffma2(acc[2][1], d2, x0.y);
                ffma2(acc[2][2], d2, x1.x); ffma2(acc[2][3], d2, x1.y);
                ffma2(acc[2][4], d2, x2.x); ffma2(acc[2][5], d2, x2.y);
                ffma2(acc[3][0], d3, x0.x); ffma2(acc[3][1], d3, x0.y);
                ffma2(acc[3][2], d3, x1.x); ffma2(acc[3][3], d3, x1.y);
                ffma2(acc[3][4], d3, x2.x); ffma2(acc[3][5], d3, x2.y);
            }
        }
    }

    const int d0w = dt * 64 + wid * 8 + rh * 4;
    const int li = lane & 15;
    #pragma unroll
    for (int q = 0; q < 4; q++)
        #pragma unroll
        for (int pp = 0; pp < 6; pp++) {
            float lo, hi;
            unpack2(acc[q][pp], lo, hi);
            lo = hsum16(lo);
            hi = hsum16(hi);
            if (li == ((q * 6 + pp) & 15)) {
                #pragma unroll
                for (int h = 0; h < 2; h++) {
                    const int j = 2 * pp + h;
                    const int m = j >> 2;
                    const int k = j & 3;
                    const int mod = (m == 0) ? 3 : (m == 1) ? 4 : 6;
                    out[(size_t)((l * 7 + mod) * 8 + 4 + k) * DM + d0w + q] =
                        h ? hi : lo;
                }
            }
        }

    // Replay-safe reset: last of the 16 consumers clears both counters.
    __syncthreads();
    if (tid == 0) {
        const int c = atomicAdd(&g_consumed[l], 1);
        if (c == 15) {
            g_consumed[l] = 0;
            g_ready[l] = 0;
            __threadfence();
        }
    }
}

// ---- Affine module: 8 warps x 8 rows; in-block x transpose to e-major ----
template <int I>
__device__ void affine_block(const float* __restrict__ xg,
                             const float* __restrict__ W,
                             float* __restrict__ out,
                             int l, int dt, int mod,
                             char* sm, uint32_t smem_u,
                             int tid, int lane, int wid)
{
    const int COLS = I / 4;
    const int S = COLS / 16;            // 16 (IQO) or 4 (IKV)
    const int rh = lane >> 4;
    const int col = lane & 15;
    const float* wbase = W + ((size_t)l * DM + dt * 64 + wid * 8) * I;
    const uint32_t wring_u = smem_u + WRING_OFF + wid * WRING_WARP;
    const char* wring = sm + WRING_OFF + wid * WRING_WARP;

    auto wstep = [&](int s) {
        if (s < S) {
            const uint32_t dst = wring_u + (s % 5) * 2048 + (rh * 64 + col) * 16;
            const float* src = wbase + (size_t)(rh * 4) * I + (s * 16 + col) * 4;
            #pragma unroll
            for (int q = 0; q < 4; q++)
                cpasync16(dst + q * 256, src + (size_t)q * I);
        }
        CP_COMMIT();
    };
    wstep(0); wstep(1); wstep(2); wstep(3);

    // One-time in-block transpose: natural x[k][i] -> e-major smem.
    {
        const float4* xn = reinterpret_cast<const float4*>(xg) + (size_t)l * I;
        float* tf = reinterpret_cast<float*>(sm);
        #pragma unroll
        for (int it = 0; it < I / 256; it++) {
            const int idx = tid + it * 256;
            const int kr = idx / COLS, cc = idx % COLS;
            float4 v = __ldcs(xn + (size_t)kr * COLS + cc);
            tf[(0 * COLS + cc) * 4 + kr] = v.x;
            tf[(1 * COLS + cc) * 4 + kr] = v.y;
            tf[(2 * COLS + cc) * 4 + kr] = v.z;
            tf[(3 * COLS + cc) * 4 + kr] = v.w;
        }
    }
    __syncthreads();

    unsigned long long acc[4][2];
    #pragma unroll
    for (int q = 0; q < 4; q++) { acc[q][0] = 0ull; acc[q][1] = 0ull; }

    for (int s = 0; s < S; ++s) {
        cp_wait3();
        const char* wq = wring + (s % 5) * 2048;
        float4 w0 = *reinterpret_cast<const float4*>(wq + (rh * 64 + 0 * 16 + col) * 16);
        float4 w1 = *reinterpret_cast<const float4*>(wq + (rh * 64 + 1 * 16 + col) * 16);
        float4 w2 = *reinterpret_cast<const float4*>(wq + (rh * 64 + 2 * 16 + col) * 16);
        float4 w3 = *reinterpret_cast<const float4*>(wq + (rh * 64 + 3 * 16 + col) * 16);
        wstep(s + 4);
        const char* xp = sm + (s * 16 + col) * 16;
        #pragma unroll
        for (int e = 0; e < 4; e++) {
            ulonglong2 xv = *reinterpret_cast<const ulonglong2*>(xp + e * (COLS * 16));
            unsigned long long d0 = fdup(getf(w0, e));
            unsigned long long d1 = fdup(getf(w1, e));
            unsigned long long d2 = fdup(getf(w2, e));
            unsigned long long d3 = fdup(getf(w3, e));
            ffma2(acc[0][0], d0, xv.x); ffma2(acc[0][1], d0, xv.y);
            ffma2(acc[1][0], d1, xv.x); ffma2(acc[1][1], d1, xv.y);
            ffma2(acc[2][0], d2, xv.x); ffma2(acc[2][1], d2, xv.y);
            ffma2(acc[3][0], d3, xv.x); ffma2(acc[3][1], d3, xv.y);
        }
    }

    const int d0w = dt * 64 + wid * 8 + rh * 4;
    const int rowb = (l * 7 + mod) * 8 + 4;
    const int li = lane & 15;
    #pragma unroll
    for (int q = 0; q < 4; q++)
        #pragma unroll
        for (int p = 0; p < 2; p++) {
            float lo, hi;
            unpack2(acc[q][p], lo, hi);
            lo = hsum16(lo);
            hi = hsum16(hi);
            if (li == (q * 4 + 2 * p))
                out[(size_t)(rowb + 2 * p) * DM + d0w + q] = lo;
            if (li == (q * 4 + 2 * p + 1))
                out[(size_t)(rowb + 2 * p + 1) * DM + d0w + q] = hi;
        }
}

__global__ __launch_bounds__(256, 2)
void bse_fused_kernel(const float* __restrict__ residual,
                      const float* __restrict__ cq,
                      const float* __restrict__ ck,
                      const float* __restrict__ cv,
                      const float* __restrict__ co,
                      const float* __restrict__ cm,
                      const float* __restrict__ Wq,
                      const float* __restrict__ Wk,
                      const float* __restrict__ Wv,
                      const float* __restrict__ Wo,
                      const float* __restrict__ Wd,
                      float* __restrict__ out)
{
    extern __shared__ __align__(16) char sm[];
    const int bid = blockIdx.x;
    const int tid = threadIdx.x;
    const int lane = tid & 31;
    const int wid = tid >> 5;
    const uint32_t smem_u = (uint32_t)__cvta_generic_to_shared(sm);

    if (bid < 352) {
        transpose_block(cm, bid, sm, tid);
    } else if (bid < 864) {
        const int a = bid - 352;
        mlp_block(Wd, out, a >> 4, a & 15, sm, smem_u, tid, lane, wid);
    } else if (bid < 1376) {
        const int a = bid - 864;
        affine_block<IQO>(cq, Wq, out, a >> 4, a & 15, 0, sm, smem_u, tid, lane, wid);
    } else if (bid < 1888) {
        const int a = bid - 1376;
        affine_block<IQO>(co, Wo, out, a >> 4, a & 15, 5, sm, smem_u, tid, lane, wid);
    } else if (bid < 2400) {
        const int a = bid - 1888;
        affine_block<IKV>(ck, Wk, out, a >> 4, a & 15, 1, sm, smem_u, tid, lane, wid);
    } else if (bid < 2912) {
        const int a = bid - 2400;
        affine_block<IKV>(cv, Wv, out, a >> 4, a & 15, 2, sm, smem_u, tid, lane, wid);
    } else {
        // Residual copy: residual[l,mod,k,:] -> out row (g*8 + k)
        const float4* src = reinterpret_cast<const float4*>(residual);
        float4* dst = reinterpret_cast<float4*>(out);
        const int n = NL * 7 * NK * (DM / 4);          // 229376 float4
        for (int e = (bid - 2912) * 256 + tid; e < n; e += NCOPY * 256) {
            const int d = e & 255;
            const int k = (e >> 8) & 3;
            const int g = e >> 10;
            dst[(size_t)(g * 8 + k) * 256 + d] = __ldcs(src + e);
        }
    }
}

extern "C" void kernel_launch(void* const* d_in, const int* in_sizes, int n_in,
                              void* d_out, int out_size)
{
    (void)in_sizes; (void)n_in; (void)out_size;
    const float* residual = (const float*)d_in[0];
    const float* cq = (const float*)d_in[1];
    const float* ck = (const float*)d_in[2];
    const float* cv = (const float*)d_in[3];
    const float* co = (const float*)d_in[4];
    const float* cm = (const float*)d_in[5];
    const float* Wq = (const float*)d_in[6];
    const float* Wk = (const float*)d_in[7];
    const float* Wv = (const float*)d_in[8];
    const float* Wo = (const float*)d_in[9];
    const float* Wd = (const float*)d_in[10];
    float* out = (float*)d_out;

    static bool attr_done = false;
    if (!attr_done) {
        cudaFuncSetAttribute(bse_fused_kernel,
                             cudaFuncAttributeMaxDynamicSharedMemorySize, SMEM_BYTES);
        attr_done = true;
    }

    bse_fused_kernel<<<2912 + NCOPY, 256, SMEM_BYTES>>>(residual, cq, ck, cv, co, cm,
                                                        Wq, Wk, Wv, Wo, Wd, out);
}

// round 16
// speedup vs baseline: 1.0170x; 1.0170x over previous
#include <cuda_runtime.h>
#include <cstdint>

#define NL 32
#define DM 1024
#define NK 4
#define IQO 1024
#define IKV 256
#define IFF 2816

#define XCHUNK_B 12288                // 768 quads, e-major: ((e*3+p)*64 + cc)*16
#define WRING_OFF (2 * XCHUNK_B)      // 24576
#define WRING_WARP 10240              // 5 slots x 2048 B
#define SMEM_BYTES (WRING_OFF + 8 * WRING_WARP)   // 106496
#define NCOPY 128

// -------- transposed MLP x scratch + replay-safe handshake --------
// quad (l*11 + c)*768 + (e*3+p)*64 + ccl = x[j=4p..4p+3] at elem ((c*64+ccl)*4+e)
__device__ float4 g_xt_mlp[NL * 11 * 768];
__device__ int g_ready[NL];       // transposes done per layer (0..11)
__device__ int g_consumed[NL];    // MLP consumers done per layer (0..16)

// -------- helpers --------
__device__ __forceinline__ void ffma2(unsigned long long &d,
                                      unsigned long long a,
                                      unsigned long long b) {
    asm("fma.rn.f32x2 %0, %1, %2, %0;" : "+l"(d) : "l"(a), "l"(b));
}
__device__ __forceinline__ unsigned long long fdup(float f) {
    unsigned long long r;
    asm("mov.b64 %0, {%1, %1};" : "=l"(r) : "f"(f));
    return r;
}
__device__ __forceinline__ void unpack2(unsigned long long v, float &lo, float &hi) {
    asm("mov.b64 {%0, %1}, %2;" : "=f"(lo), "=f"(hi) : "l"(v));
}
__device__ __forceinline__ float getf(float4 v, int e) {
    return (e == 0) ? v.x : (e == 1) ? v.y : (e == 2) ? v.z : v.w;
}
__device__ __forceinline__ float hsum16(float v) {
    v += __shfl_xor_sync(0xffffffffu, v, 8);
    v += __shfl_xor_sync(0xffffffffu, v, 4);
    v += __shfl_xor_sync(0xffffffffu, v, 2);
    v += __shfl_xor_sync(0xffffffffu, v, 1);
    return v;
}
__device__ __forceinline__ void cpasync16(uint32_t dst, const void* src) {
    asm volatile("cp.async.cg.shared.global [%0], [%1], 16;" :: "r"(dst), "l"(src));
}
#define CP_COMMIT() asm volatile("cp.async.commit_group;" ::: "memory")
__device__ __forceinline__ void cp_wait3() {
    asm volatile("cp.async.wait_group 3;" ::: "memory");
}

// ---- Transpose block: one (l, c) MLP tile, coalesced both sides ----
__device__ void transpose_block(const float* __restrict__ cm,
                                int b, char* sm, int tid)
{
    float4* tile = reinterpret_cast<float4*>(sm);
    float* tf = reinterpret_cast<float*>(sm);
    const int l = b / 11, c = b - l * 11;
    const float4* cm4 = reinterpret_cast<const float4*>(cm) +
                        (size_t)l * 12 * 704 + c * 64;
    #pragma unroll
    for (int k = 0; k < 3; k++) {
        const int idx = tid + k * 256;
        const int j = idx >> 6, ccl = idx & 63;
        float4 v = __ldcs(cm4 + (size_t)j * 704 + ccl);
        const int p = j >> 2, kk = j & 3;
        tf[((0 * 3 + p) * 64 + ccl) * 4 + kk] = v.x;
        tf[((1 * 3 + p) * 64 + ccl) * 4 + kk] = v.y;
        tf[((2 * 3 + p) * 64 + ccl) * 4 + kk] = v.z;
        tf[((3 * 3 + p) * 64 + ccl) * 4 + kk] = v.w;
    }
    __syncthreads();
    float4* dst = g_xt_mlp + (size_t)b * 768;
    #pragma unroll
    for (int k = 0; k < 3; k++) dst[tid + k * 256] = tile[tid + k * 256];
    __threadfence();
    __syncthreads();
    if (tid == 0) atomicAdd(&g_ready[l], 1);
}

// ---- MLP module: 8 warps x 8 rows = 64 rows/CTA; 12 RHS packed FFMA2 ----
__device__ void mlp_block(const float* __restrict__ Wd,
                          float* __restrict__ out,
                          int l, int dt,
                          char* sm, uint32_t smem_u,
                          int tid, int lane, int wid)
{
    // Wait for this layer's 11 transpose tiles (replay-safe counters).
    if (tid == 0) {
        while (atomicAdd(&g_ready[l], 0) < 11) { }
    }
    __syncthreads();
    __threadfence();   // acquire

    const int rh = lane >> 4;
    const int col = lane & 15;
    const float* wbase = Wd + ((size_t)l * DM + dt * 64 + wid * 8) * IFF;
    const uint32_t wring_u = smem_u + WRING_OFF + wid * WRING_WARP;
    const char* wring = sm + WRING_OFF + wid * WRING_WARP;
    const float4* xg4 = g_xt_mlp + (size_t)l * 11 * 768;

    auto wstep = [&](int s) {
        if (s < 44) {
            const uint32_t dst = wring_u + (s % 5) * 2048 + (rh * 64 + col) * 16;
            const float* src = wbase + (size_t)(rh * 4) * IFF + (s * 16 + col) * 4;
            #pragma unroll
            for (int q = 0; q < 4; q++)
                cpasync16(dst + q * 256, src + (size_t)q * IFF);
        }
        CP_COMMIT();
    };

    float4 pre[3];
    #pragma unroll
    for (int k = 0; k < 3; k++) pre[k] = xg4[tid + k * 256];

    wstep(0); wstep(1); wstep(2); wstep(3);

    unsigned long long acc[4][6];
    #pragma unroll
    for (int q = 0; q < 4; q++)
        #pragma unroll
        for (int p = 0; p < 6; p++) acc[q][p] = 0ull;

    for (int c = 0; c < 11; ++c) {
        float4* xb = reinterpret_cast<float4*>(sm + (c & 1) * XCHUNK_B);
        #pragma unroll
        for (int k = 0; k < 3; k++) xb[tid + k * 256] = pre[k];
        __syncthreads();
        if (c < 10) {
            #pragma unroll
            for (int k = 0; k < 3; k++) pre[k] = xg4[(c + 1) * 768 + tid + k * 256];
        }
        #pragma unroll
        for (int it = 0; it < 4; ++it) {
            const int s = c * 4 + it;
            cp_wait3();
            const char* wq = wring + (s % 5) * 2048;
            float4 w0 = *reinterpret_cast<const float4*>(wq + (rh * 64 + 0 * 16 + col) * 16);
            float4 w1 = *reinterpret_cast<const float4*>(wq + (rh * 64 + 1 * 16 + col) * 16);
            float4 w2 = *reinterpret_cast<const float4*>(wq + (rh * 64 + 2 * 16 + col) * 16);
            float4 w3 = *reinterpret_cast<const float4*>(wq + (rh * 64 + 3 * 16 + col) * 16);
            wstep(s + 4);
            const char* xp = reinterpret_cast<const char*>(xb) + (it * 16 + col) * 16;
            #pragma unroll
            for (int e = 0; e < 4; e++) {
                ulonglong2 x0 = *reinterpret_cast<const ulonglong2*>(xp + (e * 3 + 0) * 1024);
                ulonglong2 x1 = *reinterpret_cast<const ulonglong2*>(xp + (e * 3 + 1) * 1024);
                ulonglong2 x2 = *reinterpret_cast<const ulonglong2*>(xp + (e * 3 + 2) * 1024);
                unsigned long long d0 = fdup(getf(w0, e));
                unsigned long long d1 = fdup(getf(w1, e));
                unsigned long long d2 = fdup(getf(w2, e));
                unsigned long long d3 = fdup(getf(w3, e));
                ffma2(acc[0][0], d0, x0.x); ffma2(acc[0][1], d0, x0.y);
                ffma2(acc[0][2], d0, x1.x); ffma2(acc[0][3], d0, x1.y);
                ffma2(acc[0][4], d0, x2.x); ffma2(acc[0][5], d0, x2.y);
                ffma2(acc[1][0], d1, x0.x); ffma2(acc[1][1], d1, x0.y);
                ffma2(acc[1][2], d1, x1.x); ffma2(acc[1][3], d1, x1.y);
                ffma2(acc[1][4], d1, x2.x); ffma2(acc[1][5], d1, x2.y);
                ffma2(acc[2][0], d2, x0.x); ffma2(acc[2][1], d2, x0.y);
                ffma2(acc[2][2], d2, x1.x); ffma2(acc[2][3], d2, x1.y);
                ffma2(acc[2][4], d2, x2.x); ffma2(acc[2][5], d2, x2.y);
                ffma2(acc[3][0], d3, x0.x); ffma2(acc[3][1], d3, x0.y);
                ffma2(acc[3][2], d3, x1.x); ffma2(acc[3][3], d3, x1.y);
                ffma2(acc[3][4], d3, x2.x); ffma2(acc[3][5], d3, x2.y);
            }
        }
    }

    const int d0w = dt * 64 + wid * 8 + rh * 4;
    const int li = lane & 15;
    #pragma unroll
    for (int q = 0; q < 4; q++)
        #pragma unroll
        for (int pp = 0; pp < 6; pp++) {
            float lo, hi;
            unpack2(acc[q][pp], lo, hi);
            lo = hsum16(lo);
            hi = hsum16(hi);
            if (li == ((q * 6 + pp) & 15)) {
                #pragma unroll
                for (int h = 0; h < 2; h++) {
                    const int j = 2 * pp + h;
                    const int m = j >> 2;
                    const int k = j & 3;
                    const int mod = (m == 0) ? 3 : (m == 1) ? 4 : 6;
                    out[(size_t)((l * 7 + mod) * 8 + 4 + k) * DM + d0w + q] =
                        h ? hi : lo;
                }
            }
        }

    // Replay-safe reset: last of the 16 consumers clears both counters.
    __syncthreads();
    if (tid == 0) {
        const int c = atomicAdd(&g_consumed[l], 1);
        if (c == 15) {
            g_consumed[l] = 0;
            g_ready[l] = 0;
            __threadfence();
        }
    }
}

// ---- Affine module: 8 warps x 8 rows; in-block x transpose to e-major ----
template <int I>
__device__ void affine_block(const float* __restrict__ xg,
                             const float* __restrict__ W,
                             float* __restrict__ out,
                             int l, int dt, int mod,
                             char* sm, uint32_t smem_u,
                             int tid, int lane, int wid)
{
    const int COLS = I / 4;
    const int S = COLS / 16;            // 16 (IQO) or 4 (IKV)
    const int rh = lane >> 4;
    const int col = lane & 15;
    const float* wbase = W + ((size_t)l * DM + dt * 64 + wid * 8) * I;
    const uint32_t wring_u = smem_u + WRING_OFF + wid * WRING_WARP;
    const char* wring = sm + WRING_OFF + wid * WRING_WARP;

    auto wstep = [&](int s) {
        if (s < S) {
            const uint32_t dst = wring_u + (s % 5) * 2048 + (rh * 64 + col) * 16;
            const float* src = wbase + (size_t)(rh * 4) * I + (s * 16 + col) * 4;
            #pragma unroll
            for (int q = 0; q < 4; q++)
                cpasync16(dst + q * 256, src + (size_t)q * I);
        }
        CP_COMMIT();
    };
    wstep(0); wstep(1); wstep(2); wstep(3);

    // One-time in-block transpose: natural x[k][i] -> e-major smem.
    {
        const float4* xn = reinterpret_cast<const float4*>(xg) + (size_t)l * I;
        float* tf = reinterpret_cast<float*>(sm);
        #pragma unroll
        for (int it = 0; it < I / 256; it++) {
            const int idx = tid + it * 256;
            const int kr = idx / COLS, cc = idx % COLS;
            float4 v = __ldcs(xn + (size_t)kr * COLS + cc);
            tf[(0 * COLS + cc) * 4 + kr] = v.x;
            tf[(1 * COLS + cc) * 4 + kr] = v.y;
            tf[(2 * COLS + cc) * 4 + kr] = v.z;
            tf[(3 * COLS + cc) * 4 + kr] = v.w;
        }
    }
    __syncthreads();

    unsigned long long acc[4][2];
    #pragma unroll
    for (int q = 0; q < 4; q++) { acc[q][0] = 0ull; acc[q][1] = 0ull; }

    for (int s = 0; s < S; ++s) {
        cp_wait3();
        const char* wq = wring + (s % 5) * 2048;
        float4 w0 = *reinterpret_cast<const float4*>(wq + (rh * 64 + 0 * 16 + col) * 16);
        float4 w1 = *reinterpret_cast<const float4*>(wq + (rh * 64 + 1 * 16 + col) * 16);
        float4 w2 = *reinterpret_cast<const float4*>(wq + (rh * 64 + 2 * 16 + col) * 16);
        float4 w3 = *reinterpret_cast<const float4*>(wq + (rh * 64 + 3 * 16 + col) * 16);
        wstep(s + 4);
        const char* xp = sm + (s * 16 + col) * 16;
        #pragma unroll
        for (int e = 0; e < 4; e++) {
            ulonglong2 xv = *reinterpret_cast<const ulonglong2*>(xp + e * (COLS * 16));
            unsigned long long d0 = fdup(getf(w0, e));
            unsigned long long d1 = fdup(getf(w1, e));
            unsigned long long d2 = fdup(getf(w2, e));
            unsigned long long d3 = fdup(getf(w3, e));
            ffma2(acc[0][0], d0, xv.x); ffma2(acc[0][1], d0, xv.y);
            ffma2(acc[1][0], d1, xv.x); ffma2(acc[1][1], d1, xv.y);
            ffma2(acc[2][0], d2, xv.x); ffma2(acc[2][1], d2, xv.y);
            ffma2(acc[3][0], d3, xv.x); ffma2(acc[3][1], d3, xv.y);
        }
    }

    const int d0w = dt * 64 + wid * 8 + rh * 4;
    const int rowb = (l * 7 + mod) * 8 + 4;
    const int li = lane & 15;
    #pragma unroll
    for (int q = 0; q < 4; q++)
        #pragma unroll
        for (int p = 0; p < 2; p++) {
            float lo, hi;
            unpack2(acc[q][p], lo, hi);
            lo = hsum16(lo);
            hi = hsum16(hi);
            if (li == (q * 4 + 2 * p))
                out[(size_t)(rowb + 2 * p) * DM + d0w + q] = lo;
            if (li == (q * 4 + 2 * p + 1))
                out[(size_t)(rowb + 2 * p + 1) * DM + d0w + q] = hi;
        }
}

__global__ __launch_bounds__(256, 2)
void bse_fused_kernel(const float* __restrict__ residual,
                      const float* __restrict__ cq,
                      const float* __restrict__ ck,
                      const float* __restrict__ cv,
                      const float* __restrict__ co,
                      const float* __restrict__ cm,
                      const float* __restrict__ Wq,
                      const float* __restrict__ Wk,
                      const float* __restrict__ Wv,
                      const float* __restrict__ Wo,
                      const float* __restrict__ Wd,
                      float* __restrict__ out)
{
    extern __shared__ __align__(16) char sm[];
    const int bid = blockIdx.x;
    const int tid = threadIdx.x;
    const int lane = tid & 31;
    const int wid = tid >> 5;
    const uint32_t smem_u = (uint32_t)__cvta_generic_to_shared(sm);

    // Ramp interleave: bids 0..703 alternate transpose / Q-affine so the
    // first wave streams W_q at full DRAM rate while transposes complete.
    if (bid < 704) {
        const int h = bid >> 1;
        if ((bid & 1) == 0) {
            transpose_block(cm, h, sm, tid);
        } else {
            affine_block<IQO>(cq, Wq, out, h >> 4, h & 15, 0, sm, smem_u, tid, lane, wid);
        }
    } else if (bid < 1216) {
        const int a = bid - 704;
        mlp_block(Wd, out, a >> 4, a & 15, sm, smem_u, tid, lane, wid);
    } else if (bid < 1376) {
        const int a = 352 + (bid - 1216);          // Q tail: ids 352..511
        affine_block<IQO>(cq, Wq, out, a >> 4, a & 15, 0, sm, smem_u, tid, lane, wid);
    } else if (bid < 1888) {
        const int a = bid - 1376;
        affine_block<IQO>(co, Wo, out, a >> 4, a & 15, 5, sm, smem_u, tid, lane, wid);
    } else if (bid < 2400) {
        const int a = bid - 1888;
        affine_block<IKV>(ck, Wk, out, a >> 4, a & 15, 1, sm, smem_u, tid, lane, wid);
    } else if (bid < 2912) {
        const int a = bid - 2400;
        affine_block<IKV>(cv, Wv, out, a >> 4, a & 15, 2, sm, smem_u, tid, lane, wid);
    } else {
        // Residual copy: residual[l,mod,k,:] -> out row (g*8 + k)
        const float4* src = reinterpret_cast<const float4*>(residual);
        float4* dst = reinterpret_cast<float4*>(out);
        const int n = NL * 7 * NK * (DM / 4);          // 229376 float4
        for (int e = (bid - 2912) * 256 + tid; e < n; e += NCOPY * 256) {
            const int d = e & 255;
            const int k = (e >> 8) & 3;
            const int g = e >> 10;
            dst[(size_t)(g * 8 + k) * 256 + d] = __ldcs(src + e);
        }
    }
}

extern "C" void kernel_launch(void* const* d_in, const int* in_sizes, int n_in,
                              void* d_out, int out_size)
{
    (void)in_sizes; (void)n_in; (void)out_size;
    const float* residual = (const float*)d_in[0];
    const float* cq = (const float*)d_in[1];
    const float* ck = (const float*)d_in[2];
    const float* cv = (const float*)d_in[3];
    const float* co = (const float*)d_in[4];
    const float* cm = (const float*)d_in[5];
    const float* Wq = (const float*)d_in[6];
    const float* Wk = (const float*)d_in[7];
    const float* Wv = (const float*)d_in[8];
    const float* Wo = (const float*)d_in[9];
    const float* Wd = (const float*)d_in[10];
    float* out = (float*)d_out;

    static bool attr_done = false;
    if (!attr_done) {
        cudaFuncSetAttribute(bse_fused_kernel,
                             cudaFuncAttributeMaxDynamicSharedMemorySize, SMEM_BYTES);
        attr_done = true;
    }

    bse_fused_kernel<<<2912 + NCOPY, 256, SMEM_BYTES>>>(residual, cq, ck, cv, co, cm,
                                                        Wq, Wk, Wv, Wo, Wd, out);
}